// round 12
// baseline (speedup 1.0000x reference)
#include <cuda_runtime.h>
#include <cstdint>
#include <cstddef>

// ============================================================================
// RNNSequence: h_t = tanh(x_t @ W_ih + h_{t-1} @ W_hh + b), out[b,t,:] = h_t
// B=32, T=2048, D_IN=512, D_H=512, fp32.
//
// Phase 1: gemm_xw writes xw = x@W_ih + b into d_out (65536x512, f32x2 FMA).
// Phase 2: rnn_scan (R8 protocol, refined): 128 CTAs = 16 groups x 8 ranks.
//          W_hh slice in registers. h exchanged via L2 with per-rank
//          monotonic flags:
//            produce: __stcg h slice -> syncthreads -> st.release.gpu flag
//            consume: EACH WARP polls its own source rank's flag
//                     (ld.acquire.gpu), then immediately __ldcg-stages that
//                     rank's 16B/thread into smem -> ONE syncthreads ->
//                     compute. Per-rank poll overlaps slow producers with
//                     staging of fast ones; 2 syncs/step (R8 had 3).
//          Flags are monotonic across launches (graph-replay safe); t=0 uses
//          h=0 directly so g_h needs no initialization.
// ============================================================================

constexpr int SEQ = 2048;
constexpr int DH  = 512;

// L2-resident exchange state. g_h needs no init (t=0 reads nothing; t>=1
// reads only same-launch data). g_flag zero-init, only grows.
__device__ __align__(16) float g_h[2][16][8][2][64]; // [buf][grp][rank][batch][j]
__device__ unsigned g_flag[16][32];                   // [group][rank], padded row

__device__ __forceinline__ unsigned long long pack2(float lo, float hi) {
    unsigned long long r;
    unsigned l = __float_as_uint(lo), h = __float_as_uint(hi);
    asm("mov.b64 %0, {%1, %2};" : "=l"(r) : "r"(l), "r"(h));
    return r;
}
__device__ __forceinline__ void unpack2(unsigned long long v, float& lo, float& hi) {
    unsigned l, h;
    asm("mov.b64 {%0, %1}, %2;" : "=r"(l), "=r"(h) : "l"(v));
    lo = __uint_as_float(l);
    hi = __uint_as_float(h);
}
__device__ __forceinline__ void fma2(unsigned long long& acc,
                                     unsigned long long a, unsigned long long b) {
    asm("fma.rn.f32x2 %0, %1, %2, %0;" : "+l"(acc) : "l"(a), "l"(b));
}

// ---------------------------------------------------------------------------
// Phase 1: C[M,512] = A[M,512] @ B[512,512] + bias  (128x128x16, f32x2)
// ---------------------------------------------------------------------------
__global__ __launch_bounds__(256, 2) void gemm_xw(const float* __restrict__ A,
                                                  const float* __restrict__ B,
                                                  const float* __restrict__ bias,
                                                  float* __restrict__ C) {
    constexpr int K = 512, N = 512;
    __shared__ __align__(16) float As[16][128];
    __shared__ __align__(16) float Bs[16][128];

    const int tid  = threadIdx.x;
    const int row0 = blockIdx.y * 128;
    const int col0 = blockIdx.x * 128;
    const int ty   = tid >> 4;
    const int tx   = tid & 15;

    unsigned long long acc2[8][4];
#pragma unroll
    for (int i = 0; i < 8; i++)
#pragma unroll
        for (int j = 0; j < 4; j++) acc2[i][j] = 0ULL;

    for (int k0 = 0; k0 < K; k0 += 16) {
#pragma unroll
        for (int i = 0; i < 2; i++) {
            int s  = tid + i * 256;
            int m  = s & 127;
            int kg = (s >> 7) << 2;
            float4 v = *(const float4*)(A + (size_t)(row0 + m) * K + (k0 + kg));
            As[kg + 0][m] = v.x;
            As[kg + 1][m] = v.y;
            As[kg + 2][m] = v.z;
            As[kg + 3][m] = v.w;
        }
#pragma unroll
        for (int i = 0; i < 2; i++) {
            int s  = tid + i * 256;
            int n4 = (s & 31) << 2;
            int kk = s >> 5;
            *(float4*)(&Bs[kk][n4]) =
                *(const float4*)(B + (size_t)(k0 + kk) * N + col0 + n4);
        }
        __syncthreads();

#pragma unroll
        for (int kk = 0; kk < 16; kk++) {
            float a[8];
            *(float4*)(a)     = *(const float4*)(&As[kk][ty * 8]);
            *(float4*)(a + 4) = *(const float4*)(&As[kk][ty * 8 + 4]);
            ulonglong2 b01 = *(const ulonglong2*)(&Bs[kk][tx * 8]);
            ulonglong2 b23 = *(const ulonglong2*)(&Bs[kk][tx * 8 + 4]);
            unsigned long long bb[4] = {b01.x, b01.y, b23.x, b23.y};
#pragma unroll
            for (int i = 0; i < 8; i++) {
                unsigned au = __float_as_uint(a[i]);
                unsigned long long ad;
                asm("mov.b64 %0, {%1, %1};" : "=l"(ad) : "r"(au));
#pragma unroll
                for (int j2 = 0; j2 < 4; j2++) fma2(acc2[i][j2], ad, bb[j2]);
            }
        }
        __syncthreads();
    }

    float bv[8];
    *(float4*)(bv)     = *(const float4*)(bias + col0 + tx * 8);
    *(float4*)(bv + 4) = *(const float4*)(bias + col0 + tx * 8 + 4);

#pragma unroll
    for (int i = 0; i < 8; i++) {
        float o[8];
#pragma unroll
        for (int j2 = 0; j2 < 4; j2++) {
            float lo, hi;
            unpack2(acc2[i][j2], lo, hi);
            o[j2 * 2]     = lo + bv[j2 * 2];
            o[j2 * 2 + 1] = hi + bv[j2 * 2 + 1];
        }
        float* cp = C + (size_t)(row0 + ty * 8 + i) * N + col0 + tx * 8;
        *(float4*)(cp)     = *(float4*)(o);
        *(float4*)(cp + 4) = *(float4*)(o + 4);
    }
}

// ---------------------------------------------------------------------------
// Phase 2: L2 flag-pipelined scan, per-rank fused poll+stage
// ---------------------------------------------------------------------------
constexpr int RSTRIDE = 132;   // smem rank stride (floats): conflict-free phases

__device__ __forceinline__ float tanh_precise(float x) {
    float ax = fabsf(x);
    float em = expm1f(-2.0f * ax);
    float r  = -em / (2.0f + em);
    return copysignf(r, x);
}

__device__ __forceinline__ unsigned ld_acquire_gpu(const unsigned* p) {
    unsigned v;
    asm volatile("ld.acquire.gpu.u32 %0, [%1];" : "=r"(v) : "l"(p) : "memory");
    return v;
}
__device__ __forceinline__ void st_release_gpu(unsigned* p, unsigned v) {
    asm volatile("st.release.gpu.u32 [%0], %1;" :: "l"(p), "r"(v) : "memory");
}

__global__ __launch_bounds__(256, 1) void rnn_scan(float* __restrict__ out,
                                                   const float* __restrict__ Whh) {
    __shared__ __align__(16) float hs[2][8 * RSTRIDE];

    const int tid = threadIdx.x;
    const int r   = blockIdx.x & 7;     // rank in group
    const int g   = blockIdx.x >> 3;    // group id (0..15)

    const int j   = tid >> 2;           // 0..63
    const int kq  = tid & 3;            // 0..3
    const int col = r * 64 + j;
    const int k0  = kq * 128;

    // W_hh slice in registers: w2[i] = (Whh[k0+2i][col], Whh[k0+2i+1][col])
    unsigned long long w2[64];
#pragma unroll
    for (int i = 0; i < 64; i++) {
        float lo = Whh[(size_t)(k0 + 2 * i)     * 512 + col];
        float hi = Whh[(size_t)(k0 + 2 * i + 1) * 512 + col];
        w2[i] = pack2(lo, hi);
    }

    // Monotonic flag base: quiescent at launch; all group flags are equal
    // here (every launch advances each flag by exactly SEQ-1).
    const unsigned base = *(volatile unsigned*)&g_flag[g][r];
    unsigned* const flags = &g_flag[g][0];

    // writer role: kq==0 -> batch 2g, kq==1 -> batch 2g+1
    const int batch = (kq < 2) ? kq : 0;
    float* outp = out + ((size_t)(g * 2 + batch) * SEQ) * DH + col;
    float* const hw[2] = { &g_h[0][g][r][0][0], &g_h[1][g][r][0][0] };

    // stage role: warp w handles SOURCE rank w: polls flags[w], stages its
    // 512B block (16B per lane) into the padded smem row.
    const int srank = tid >> 5;          // 0..7 == warp id
    const int sw    = tid & 31;
    const float4* const ssrc[2] = {
        (const float4*)&g_h[0][g][0][0][0] + tid,
        (const float4*)&g_h[1][g][0][0][0] + tid
    };
    float* const sdst = (float*)hs + srank * RSTRIDE + sw * 4;

    // xw prefetch pipeline (one step ahead)
    float xw_next = 0.0f;
    if (kq < 2) xw_next = __ldg(outp);

    for (int t = 0; t < SEQ; ++t) {
        const int cur = t & 1;
        const int nb  = cur ^ 1;

        float xwv = xw_next;
        if (kq < 2 && t + 1 < SEQ) xw_next = __ldg(outp + (size_t)(t + 1) * DH);

        float pA = 0.0f, pB = 0.0f;
        if (t > 0) {
            // Fused poll+stage: wait only for OUR source rank, then stage it.
            const unsigned target = base + (unsigned)t;
            while ((int)(ld_acquire_gpu(flags + srank) - target) < 0) {}
            float4 v = __ldcg(ssrc[cur]);           // acquire orders this load
            *(float4*)(sdst + cur * (8 * RSTRIDE)) = v;
            __syncthreads();   // sync #1: hs[cur] fully staged

            const float* hb = hs[cur];
            const ulonglong2* pa0 = (const ulonglong2*)(hb + (2 * kq)     * RSTRIDE);
            const ulonglong2* pa1 = (const ulonglong2*)(hb + (2 * kq + 1) * RSTRIDE);
            const ulonglong2* pb0 = (const ulonglong2*)(hb + (2 * kq)     * RSTRIDE + 64);
            const ulonglong2* pb1 = (const ulonglong2*)(hb + (2 * kq + 1) * RSTRIDE + 64);

            unsigned long long aA0 = 0ULL, aA1 = 0ULL, aB0 = 0ULL, aB1 = 0ULL;
#pragma unroll
            for (int i = 0; i < 16; i++) {
                ulonglong2 xa = pa0[i];
                ulonglong2 xb = pa1[i];
                ulonglong2 ya = pb0[i];
                ulonglong2 yb = pb1[i];
                fma2(aA0, w2[2 * i],          xa.x);
                fma2(aA0, w2[2 * i + 1],      xa.y);
                fma2(aA1, w2[32 + 2 * i],     xb.x);
                fma2(aA1, w2[32 + 2 * i + 1], xb.y);
                fma2(aB0, w2[2 * i],          ya.x);
                fma2(aB0, w2[2 * i + 1],      ya.y);
                fma2(aB1, w2[32 + 2 * i],     yb.x);
                fma2(aB1, w2[32 + 2 * i + 1], yb.y);
            }
            float a0l, a0h, a1l, a1h, b0l, b0h, b1l, b1h;
            unpack2(aA0, a0l, a0h);
            unpack2(aA1, a1l, a1h);
            unpack2(aB0, b0l, b0h);
            unpack2(aB1, b1l, b1h);
            pA = (a0l + a0h) + (a1l + a1h);
            pB = (b0l + b0h) + (b1l + b1h);
            pA += __shfl_xor_sync(0xffffffffu, pA, 1);
            pB += __shfl_xor_sync(0xffffffffu, pB, 1);
            pA += __shfl_xor_sync(0xffffffffu, pA, 2);
            pB += __shfl_xor_sync(0xffffffffu, pB, 2);
        }

        float hn = 0.0f;
        if (kq < 2) {
            float s = (kq == 0 ? pA : pB) + xwv;    // t==0: pA=pB=0
            hn = tanh_precise(s);
            if (t < SEQ - 1)
                __stcg(hw[nb] + kq * 64 + j, hn);   // publish o_t slice first
        }

        if (t < SEQ - 1) {
            // sync #2: all publish stores issued CTA-wide; then release flag.
            // Overwrite safety: our buf[nb] store at t follows sync#1(t),
            // which follows every peer's flag >= base+t, i.e. every peer
            // finished staging buf[nb]'s o_{t-2} content at its step t-1.
            __syncthreads();
            if (tid == 0)
                st_release_gpu(flags + r, base + (unsigned)(t + 1));
        }

        // DRAM output store AFTER the release: off the critical path.
        if (kq < 2) outp[(size_t)t * DH] = hn;
    }
}

// ---------------------------------------------------------------------------
// Launch
// ---------------------------------------------------------------------------
extern "C" void kernel_launch(void* const* d_in, const int* in_sizes, int n_in,
                              void* d_out, int out_size) {
    const float* x    = (const float*)d_in[0];  // [32,2048,512]
    const float* W_ih = (const float*)d_in[1];  // [512,512]
    const float* W_hh = (const float*)d_in[2];  // [512,512]
    const float* bias = (const float*)d_in[3];  // [512]
    float* out = (float*)d_out;                 // [32,2048,512]

    dim3 ggrid(512 / 128, (32 * SEQ) / 128);    // (4, 512)
    gemm_xw<<<ggrid, 256>>>(x, W_ih, bias, out);

    // 128 plain CTAs (single wave on 148 SMs — required for spin safety).
    rnn_scan<<<128, 256>>>(out, W_hh);
}

// round 13
// speedup vs baseline: 1.0986x; 1.0986x over previous
#include <cuda_runtime.h>
#include <cstdint>
#include <cstddef>

// ============================================================================
// RNNSequence: h_t = tanh(x_t @ W_ih + h_{t-1} @ W_hh + b), out[b,t,:] = h_t
// B=32, T=2048, D_IN=512, D_H=512, fp32.
//
// Phase 1: gemm_xw writes xw = x@W_ih + b into d_out. Register-prefetch
//          pipeline: next K-tile's LDGs issue right after syncthreads and
//          complete under the current tile's FMA work.
// Phase 2: rnn_scan — R8 protocol EXACTLY (the proven fastest exchange):
//          128 CTAs = 16 groups x 8 ranks; W_hh slice in registers; L2 flag
//          exchange (8-lane acquire poll -> stage 4KB -> compute -> release).
//          This round: fast tanh (__expf + __fdividef), 3-shuffle paired
//          reduction, publish ASAP, DRAM out-store after the release.
// ============================================================================

constexpr int SEQ = 2048;
constexpr int DH  = 512;

// L2-resident exchange state. g_h needs no init (t=0 reads nothing; t>=1 reads
// only same-launch data). g_flag zero-init, only grows (graph-replay safe).
__device__ __align__(16) float g_h[2][16][8][2][64]; // [buf][grp][rank][batch][j]
__device__ unsigned g_flag[16][32];                   // [group][rank], padded row

__device__ __forceinline__ unsigned long long pack2(float lo, float hi) {
    unsigned long long r;
    unsigned l = __float_as_uint(lo), h = __float_as_uint(hi);
    asm("mov.b64 %0, {%1, %2};" : "=l"(r) : "r"(l), "r"(h));
    return r;
}
__device__ __forceinline__ void unpack2(unsigned long long v, float& lo, float& hi) {
    unsigned l, h;
    asm("mov.b64 {%0, %1}, %2;" : "=r"(l), "=r"(h) : "l"(v));
    lo = __uint_as_float(l);
    hi = __uint_as_float(h);
}
__device__ __forceinline__ void fma2(unsigned long long& acc,
                                     unsigned long long a, unsigned long long b) {
    asm("fma.rn.f32x2 %0, %1, %2, %0;" : "+l"(acc) : "l"(a), "l"(b));
}

// ---------------------------------------------------------------------------
// Phase 1: C[M,512] = A[M,512] @ B[512,512] + bias (128x128x16, reg-prefetch)
// ---------------------------------------------------------------------------
__global__ __launch_bounds__(256, 2) void gemm_xw(const float* __restrict__ A,
                                                  const float* __restrict__ B,
                                                  const float* __restrict__ bias,
                                                  float* __restrict__ C) {
    constexpr int K = 512, N = 512;
    __shared__ __align__(16) float As[16][128];
    __shared__ __align__(16) float Bs[16][128];

    const int tid  = threadIdx.x;
    const int row0 = blockIdx.y * 128;
    const int col0 = blockIdx.x * 128;
    const int ty   = tid >> 4;
    const int tx   = tid & 15;

    // per-thread tile-load geometry (two slots each for A and B)
    const int m0  = tid & 127;                 // slot 0/1 share m (s=tid, tid+256)
    const int m1  = (tid + 256) & 127;
    const int kg0 = ((tid) >> 7) << 2;
    const int kg1 = ((tid + 256) >> 7) << 2;
    const int bn0 = (tid & 31) << 2;
    const int bk0 = tid >> 5;
    const int bn1 = ((tid + 256) & 31) << 2;
    const int bk1 = (tid + 256) >> 5;

    float4 rA0, rA1, rB0, rB1;
    // preload tile k0=0
    rA0 = *(const float4*)(A + (size_t)(row0 + m0) * K + kg0);
    rA1 = *(const float4*)(A + (size_t)(row0 + m1) * K + kg1);
    rB0 = *(const float4*)(B + (size_t)bk0 * N + col0 + bn0);
    rB1 = *(const float4*)(B + (size_t)bk1 * N + col0 + bn1);

    unsigned long long acc2[8][4];
#pragma unroll
    for (int i = 0; i < 8; i++)
#pragma unroll
        for (int j = 0; j < 4; j++) acc2[i][j] = 0ULL;

    for (int k0 = 0; k0 < K; k0 += 16) {
        // STS staged registers (tile k0)
        As[kg0 + 0][m0] = rA0.x; As[kg0 + 1][m0] = rA0.y;
        As[kg0 + 2][m0] = rA0.z; As[kg0 + 3][m0] = rA0.w;
        As[kg1 + 0][m1] = rA1.x; As[kg1 + 1][m1] = rA1.y;
        As[kg1 + 2][m1] = rA1.z; As[kg1 + 3][m1] = rA1.w;
        *(float4*)(&Bs[bk0][bn0]) = rB0;
        *(float4*)(&Bs[bk1][bn1]) = rB1;
        __syncthreads();

        // issue next tile's LDGs; latency hidden under the FMA work below
        if (k0 + 16 < K) {
            rA0 = *(const float4*)(A + (size_t)(row0 + m0) * K + (k0 + 16 + kg0));
            rA1 = *(const float4*)(A + (size_t)(row0 + m1) * K + (k0 + 16 + kg1));
            rB0 = *(const float4*)(B + (size_t)(k0 + 16 + bk0) * N + col0 + bn0);
            rB1 = *(const float4*)(B + (size_t)(k0 + 16 + bk1) * N + col0 + bn1);
        }

#pragma unroll
        for (int kk = 0; kk < 16; kk++) {
            float a[8];
            *(float4*)(a)     = *(const float4*)(&As[kk][ty * 8]);
            *(float4*)(a + 4) = *(const float4*)(&As[kk][ty * 8 + 4]);
            ulonglong2 b01 = *(const ulonglong2*)(&Bs[kk][tx * 8]);
            ulonglong2 b23 = *(const ulonglong2*)(&Bs[kk][tx * 8 + 4]);
            unsigned long long bb[4] = {b01.x, b01.y, b23.x, b23.y};
#pragma unroll
            for (int i = 0; i < 8; i++) {
                unsigned au = __float_as_uint(a[i]);
                unsigned long long ad;
                asm("mov.b64 %0, {%1, %1};" : "=l"(ad) : "r"(au));
#pragma unroll
                for (int j2 = 0; j2 < 4; j2++) fma2(acc2[i][j2], ad, bb[j2]);
            }
        }
        __syncthreads();
    }

    float bv[8];
    *(float4*)(bv)     = *(const float4*)(bias + col0 + tx * 8);
    *(float4*)(bv + 4) = *(const float4*)(bias + col0 + tx * 8 + 4);

#pragma unroll
    for (int i = 0; i < 8; i++) {
        float o[8];
#pragma unroll
        for (int j2 = 0; j2 < 4; j2++) {
            float lo, hi;
            unpack2(acc2[i][j2], lo, hi);
            o[j2 * 2]     = lo + bv[j2 * 2];
            o[j2 * 2 + 1] = hi + bv[j2 * 2 + 1];
        }
        float* cp = C + (size_t)(row0 + ty * 8 + i) * N + col0 + tx * 8;
        *(float4*)(cp)     = *(float4*)(o);
        *(float4*)(cp + 4) = *(float4*)(o + 4);
    }
}

// ---------------------------------------------------------------------------
// Phase 2: L2 flag-pipelined scan (R8 protocol)
// ---------------------------------------------------------------------------
constexpr int RSTRIDE = 132;   // smem rank stride (floats): conflict-free phases

// Fast tanh: MUFU-based (EX2 + RCP). Abs err ~1e-7; deterministic.
__device__ __forceinline__ float tanh_fast(float x) {
    float e = __expf(2.0f * fabsf(x));            // inf for large x -> r = 1
    float r = 1.0f - __fdividef(2.0f, e + 1.0f);
    return copysignf(r, x);
}

__device__ __forceinline__ unsigned ld_acquire_gpu(const unsigned* p) {
    unsigned v;
    asm volatile("ld.acquire.gpu.u32 %0, [%1];" : "=r"(v) : "l"(p) : "memory");
    return v;
}
__device__ __forceinline__ void st_release_gpu(unsigned* p, unsigned v) {
    asm volatile("st.release.gpu.u32 [%0], %1;" :: "l"(p), "r"(v) : "memory");
}

__global__ __launch_bounds__(256, 1) void rnn_scan(float* __restrict__ out,
                                                   const float* __restrict__ Whh) {
    __shared__ __align__(16) float hs[8 * RSTRIDE];

    const int tid = threadIdx.x;
    const int r   = blockIdx.x & 7;     // rank in group
    const int g   = blockIdx.x >> 3;    // group id (0..15)

    const int j   = tid >> 2;           // 0..63
    const int kq  = tid & 3;            // 0..3
    const int col = r * 64 + j;
    const int k0  = kq * 128;

    // W_hh slice in registers: w2[i] = (Whh[k0+2i][col], Whh[k0+2i+1][col])
    unsigned long long w2[64];
#pragma unroll
    for (int i = 0; i < 64; i++) {
        float lo = Whh[(size_t)(k0 + 2 * i)     * 512 + col];
        float hi = Whh[(size_t)(k0 + 2 * i + 1) * 512 + col];
        w2[i] = pack2(lo, hi);
    }

    // Monotonic flag base: quiescent at launch; only this CTA writes its flag.
    const unsigned base = *(volatile unsigned*)&g_flag[g][r];
    unsigned* const flags = &g_flag[g][0];

    // writer role: kq==0 -> batch 2g, kq==1 -> batch 2g+1
    const int batch = (kq < 2) ? kq : 0;
    float* outp = out + ((size_t)(g * 2 + batch) * SEQ) * DH + col;
    float* const hw[2] = { &g_h[0][g][r][0][0], &g_h[1][g][r][0][0] };

    // stage role (R8): warp w stages rank w's 512B block, 16B per lane
    const int srank = tid >> 5;
    const int sw    = tid & 31;
    const float4* const ssrc[2] = {
        (const float4*)&g_h[0][g][0][0][0] + tid,
        (const float4*)&g_h[1][g][0][0][0] + tid
    };
    float* const sdst = (float*)hs + srank * RSTRIDE + sw * 4;

    // xw prefetch pipeline (one step ahead)
    float xw_next = 0.0f;
    if (kq < 2) xw_next = __ldg(outp);

    for (int t = 0; t < SEQ; ++t) {
        const int cur = t & 1;
        const int nb  = cur ^ 1;

        float xwv = xw_next;
        if (kq < 2 && t + 1 < SEQ) xw_next = __ldg(outp + (size_t)(t + 1) * DH);

        float sum = 0.0f;
        if (t > 0) {
            // Wait: all 8 ranks published o_{t-1} (flag >= base+t).  (R8)
            if (tid < 8) {
                const unsigned target = base + (unsigned)t;
                while ((int)(ld_acquire_gpu(flags + tid) - target) < 0) {}
            }
            __syncthreads();
            // Stage 4KB of o_{t-1} from L2 into padded smem.  (R8)
            float4 v = __ldcg(ssrc[cur]);
            *(float4*)sdst = v;
            __syncthreads();

            const float* hb = hs;
            const ulonglong2* pa0 = (const ulonglong2*)(hb + (2 * kq)     * RSTRIDE);
            const ulonglong2* pa1 = (const ulonglong2*)(hb + (2 * kq + 1) * RSTRIDE);
            const ulonglong2* pb0 = (const ulonglong2*)(hb + (2 * kq)     * RSTRIDE + 64);
            const ulonglong2* pb1 = (const ulonglong2*)(hb + (2 * kq + 1) * RSTRIDE + 64);

            unsigned long long aA0 = 0ULL, aA1 = 0ULL, aB0 = 0ULL, aB1 = 0ULL;
#pragma unroll
            for (int i = 0; i < 16; i++) {
                ulonglong2 xa = pa0[i];
                ulonglong2 xb = pa1[i];
                ulonglong2 ya = pb0[i];
                ulonglong2 yb = pb1[i];
                fma2(aA0, w2[2 * i],          xa.x);
                fma2(aA0, w2[2 * i + 1],      xa.y);
                fma2(aA1, w2[32 + 2 * i],     xb.x);
                fma2(aA1, w2[32 + 2 * i + 1], xb.y);
                fma2(aB0, w2[2 * i],          ya.x);
                fma2(aB0, w2[2 * i + 1],      ya.y);
                fma2(aB1, w2[32 + 2 * i],     yb.x);
                fma2(aB1, w2[32 + 2 * i + 1], yb.y);
            }
            float a0l, a0h, a1l, a1h, b0l, b0h, b1l, b1h;
            unpack2(aA0, a0l, a0h);
            unpack2(aA1, a1l, a1h);
            unpack2(aB0, b0l, b0h);
            unpack2(aB1, b1l, b1h);
            float pA = (a0l + a0h) + (a1l + a1h);
            float pB = (b0l + b0h) + (b1l + b1h);
            // paired 3-shuffle reduction: lane kq=0 ends with full A sum,
            // lane kq=1 with full B sum.
            float u = (kq & 1) ? pB : pA;
            float v2 = (kq & 1) ? pA : pB;
            u += __shfl_xor_sync(0xffffffffu, v2, 1);
            u += __shfl_xor_sync(0xffffffffu, u, 2);
            sum = u;
        }

        float hn = 0.0f;
        if (kq < 2) {
            hn = tanh_fast(sum + xwv);              // t==0: sum=0
            if (t < SEQ - 1)
                __stcg(hw[nb] + kq * 64 + j, hn);   // publish FIRST (critical)
        }

        if (t < SEQ - 1) {
            __syncthreads();   // all publish stores issued CTA-wide (R8)
            if (tid == 0)
                st_release_gpu(flags + r, base + (unsigned)(t + 1));
        }

        // DRAM output store AFTER the release: off the critical path.
        if (kq < 2) outp[(size_t)t * DH] = hn;
    }
}

// ---------------------------------------------------------------------------
// Launch
// ---------------------------------------------------------------------------
extern "C" void kernel_launch(void* const* d_in, const int* in_sizes, int n_in,
                              void* d_out, int out_size) {
    const float* x    = (const float*)d_in[0];  // [32,2048,512]
    const float* W_ih = (const float*)d_in[1];  // [512,512]
    const float* W_hh = (const float*)d_in[2];  // [512,512]
    const float* bias = (const float*)d_in[3];  // [512]
    float* out = (float*)d_out;                 // [32,2048,512]

    dim3 ggrid(512 / 128, (32 * SEQ) / 128);    // (4, 512)
    gemm_xw<<<ggrid, 256>>>(x, W_ih, bias, out);

    // 128 plain CTAs (single wave on 148 SMs — required for spin safety).
    rnn_scan<<<128, 256>>>(out, W_hh);
}